// round 10
// baseline (speedup 1.0000x reference)
#include <cuda_runtime.h>
#include <cuda_fp16.h>

#define NN 100000
#define NE 1600000
#define SCAN_B 1024
#define NBLK ((NN + SCAN_B - 1) / SCAN_B)   // 98

// ---------------- scratch (static device globals; no runtime allocation) ----
__device__ unsigned g_Hs1h[NN * 64]; // (x@W1)*dinv, half2 pairs [N,128ch]
__device__ unsigned g_hh  [NN * 64]; // relu(layer1), half2 pairs [N,128ch]
__device__ unsigned g_Hs2h[NN * 32]; // (h@W2)*dinv, half2       [N,64ch]
__device__ int   g_count[NN];
__device__ float g_dinv[NN];
__device__ int   g_rowptr[NN + 1];
__device__ int   g_cursor[NN];
__device__ int   g_colidx[NE];
__device__ unsigned long long g_sdesc[NBLK]; // scan lookback: (status<<32)|value
__device__ int   g_is64;            // 1 if edge_index is int64, 0 if int32

// ---------------- f32x2 helpers --------------------------------------------
__device__ __forceinline__ unsigned long long pack2(float a, float b) {
    unsigned long long r;
    asm("mov.b64 %0, {%1, %2};" : "=l"(r) : "f"(a), "f"(b));
    return r;
}
__device__ __forceinline__ void fma2(unsigned long long& d,
                                     unsigned long long a,
                                     unsigned long long b) {
    asm("fma.rn.f32x2 %0, %1, %2, %0;" : "+l"(d) : "l"(a), "l"(b));
}
__device__ __forceinline__ float2 unpack2(unsigned long long v) {
    float2 f;
    asm("mov.b64 {%0, %1}, %2;" : "=f"(f.x), "=f"(f.y) : "l"(v));
    return f;
}

// ---------------- edge dtype detection --------------------------------------
__global__ void k_detect(const int* __restrict__ ei32) {
    __shared__ int s_or;
    if (threadIdx.x == 0) s_or = 0;
    __syncthreads();
    int v = ei32[2 * threadIdx.x + 1];
    if (v != 0) atomicOr(&s_or, 1);
    __syncthreads();
    if (threadIdx.x == 0) g_is64 = (s_or == 0) ? 1 : 0;
}

// ---------------- CSR build -------------------------------------------------
__global__ void k_zero() {
    int i = blockIdx.x * blockDim.x + threadIdx.x;
    if (i < NN) g_count[i] = 0;
    if (i < NBLK) g_sdesc[i] = 0ull;
}

// 4 edges per thread, vectorized index loads
__global__ void k_hist(const void* __restrict__ ei) {
    int q = blockIdx.x * blockDim.x + threadIdx.x;
    if (q >= NE / 4) return;
    int d0, d1, d2, d3;
    if (g_is64) {
        const long long* p = (const long long*)ei + NE + 4 * q;
        d0 = (int)p[0]; d1 = (int)p[1]; d2 = (int)p[2]; d3 = (int)p[3];
    } else {
        int4 v = ((const int4*)((const int*)ei + NE))[q];
        d0 = v.x; d1 = v.y; d2 = v.z; d3 = v.w;
    }
    if ((unsigned)d0 < (unsigned)NN) atomicAdd(&g_count[d0], 1);
    if ((unsigned)d1 < (unsigned)NN) atomicAdd(&g_count[d1], 1);
    if ((unsigned)d2 < (unsigned)NN) atomicAdd(&g_count[d2], 1);
    if ((unsigned)d3 < (unsigned)NN) atomicAdd(&g_count[d3], 1);
}

// Fused single-pass scan with decoupled lookback. 98 blocks, all resident in
// wave 1 (<=148 SMs), so the predecessor spin cannot deadlock. Status+value
// live in one 64-bit word so aggregate->prefix upgrade is race-free.
__global__ void k_scan() {
    __shared__ int s[SCAN_B];
    __shared__ int s_prev;
    int t = threadIdx.x, b = blockIdx.x;
    int i = b * SCAN_B + t;
    int v = (i < NN) ? g_count[i] : 0;
    s[t] = v;
    __syncthreads();
    for (int off = 1; off < SCAN_B; off <<= 1) {
        int x = (t >= off) ? s[t - off] : 0;
        __syncthreads();
        s[t] += x;
        __syncthreads();
    }
    if (t == 0) {
        int total = s[SCAN_B - 1];
        if (b == 0) {
            atomicExch(&g_sdesc[0], (2ull << 32) | (unsigned)total);
            s_prev = 0;
        } else {
            atomicExch(&g_sdesc[b], (1ull << 32) | (unsigned)total);
            int prev = 0;
            int j = b - 1;
            while (true) {
                unsigned long long d;
                do { d = atomicAdd(&g_sdesc[j], 0ull); } while ((d >> 32) == 0);
                prev += (int)(unsigned)d;
                if ((d >> 32) == 2) break;
                j--;
            }
            atomicExch(&g_sdesc[b], (2ull << 32) | (unsigned)(prev + total));
            s_prev = prev;
        }
    }
    __syncthreads();
    int excl = s[t] - v + s_prev;
    if (i < NN) {
        g_rowptr[i] = excl;
        g_cursor[i] = excl;
        g_dinv[i]   = rsqrtf((float)(v + 1));
    }
    if (i == NN - 1) g_rowptr[NN] = NE;
}

__global__ void k_scatter(const void* __restrict__ ei) {
    int q = blockIdx.x * blockDim.x + threadIdx.x;
    if (q >= NE / 4) return;
    int s0, s1, s2, s3, d0, d1, d2, d3;
    if (g_is64) {
        const long long* ps = (const long long*)ei + 4 * q;
        const long long* pd = (const long long*)ei + NE + 4 * q;
        s0 = (int)ps[0]; s1 = (int)ps[1]; s2 = (int)ps[2]; s3 = (int)ps[3];
        d0 = (int)pd[0]; d1 = (int)pd[1]; d2 = (int)pd[2]; d3 = (int)pd[3];
    } else {
        int4 vs = ((const int4*)ei)[q];
        int4 vd = ((const int4*)((const int*)ei + NE))[q];
        s0 = vs.x; s1 = vs.y; s2 = vs.z; s3 = vs.w;
        d0 = vd.x; d1 = vd.y; d2 = vd.z; d3 = vd.w;
    }
#define SCAT(ss, dd) \
    if ((unsigned)(dd) < (unsigned)NN && (unsigned)(ss) < (unsigned)NN) { \
        int pos = atomicAdd(&g_cursor[dd], 1); \
        if ((unsigned)pos < (unsigned)NE) g_colidx[pos] = (ss); }
    SCAT(s0, d0) SCAT(s1, d1) SCAT(s2, d2) SCAT(s3, d3)
#undef SCAT
}

// ---------------- GEMM:  Hs[m, BN] = (A[m, :128] @ W[:128, :BN]) * dinv[m] --
// 64 rows/block, 256 threads = (ty 0..7 -> 8 rows) x (tx 0..31 -> BN cols)
// BN==128: A = x (fp32 arg)   -> writes g_Hs1h (fp16).
// BN==64 : A = g_hh (fp16)    -> writes g_Hs2h (fp16).
template <int BN>
__global__ void k_gemm(const float* __restrict__ Ain,
                       const float* __restrict__ W) {
    __shared__ float As[64 * 128];   // 32 KB
    const int tid = threadIdx.x;
    const int tx = tid & 31, ty = tid >> 5;
    const int rowBase = blockIdx.x * 64;

    if constexpr (BN == 128) {   // stage A tile from fp32 x
        const float4* A4 = (const float4*)Ain;
        float4* As4 = (float4*)As;
#pragma unroll
        for (int i = 0; i < 8; i++) {
            int f = tid + i * 256;
            int r = f >> 5, c4 = f & 31;
            int gr = rowBase + r;
            As4[f] = (gr < NN) ? A4[gr * 32 + c4] : make_float4(0.f, 0.f, 0.f, 0.f);
        }
    } else {                     // stage A tile from fp16 g_hh, convert to f32
        const uint4* A4 = (const uint4*)g_hh;   // 8 halves per uint4
#pragma unroll
        for (int i = 0; i < 4; i++) {
            int f = tid + i * 256;               // 0..1023
            int r = f >> 4, c = f & 15;          // 16 uint4 per 128-ch row
            int gr = rowBase + r;
            uint4 u = (gr < NN) ? A4[gr * 16 + c] : make_uint4(0, 0, 0, 0);
            float2 p0 = __half22float2(*(__half2*)&u.x);
            float2 p1 = __half22float2(*(__half2*)&u.y);
            float2 p2 = __half22float2(*(__half2*)&u.z);
            float2 p3 = __half22float2(*(__half2*)&u.w);
            float4* dst = (float4*)&As[r * 128 + c * 8];
            dst[0] = make_float4(p0.x, p0.y, p1.x, p1.y);
            dst[1] = make_float4(p2.x, p2.y, p3.x, p3.y);
        }
    }
    __syncthreads();

    constexpr int NP = BN / 64;
    unsigned long long acc[8][NP];
#pragma unroll
    for (int r = 0; r < 8; r++)
#pragma unroll
        for (int p = 0; p < NP; p++) acc[r][p] = 0ull;

    const float4* As4 = (const float4*)As;

#pragma unroll 4
    for (int k = 0; k < 128; k += 4) {
        unsigned long long breg[4][NP];
#pragma unroll
        for (int kk = 0; kk < 4; kk++) {
            if constexpr (NP == 2) {
                ulonglong2 bb = __ldg(&((const ulonglong2*)W)[(k + kk) * 32 + tx]);
                breg[kk][0] = bb.x; breg[kk][1] = bb.y;
            } else {
                breg[kk][0] = __ldg(&((const unsigned long long*)W)[(k + kk) * 32 + tx]);
            }
        }
#pragma unroll
        for (int r = 0; r < 8; r++) {
            float4 a4 = As4[(ty * 8 + r) * 32 + (k >> 2)];
            unsigned long long aa;
            aa = pack2(a4.x, a4.x);
#pragma unroll
            for (int p = 0; p < NP; p++) fma2(acc[r][p], aa, breg[0][p]);
            aa = pack2(a4.y, a4.y);
#pragma unroll
            for (int p = 0; p < NP; p++) fma2(acc[r][p], aa, breg[1][p]);
            aa = pack2(a4.z, a4.z);
#pragma unroll
            for (int p = 0; p < NP; p++) fma2(acc[r][p], aa, breg[2][p]);
            aa = pack2(a4.w, a4.w);
#pragma unroll
            for (int p = 0; p < NP; p++) fma2(acc[r][p], aa, breg[3][p]);
        }
    }

#pragma unroll
    for (int r = 0; r < 8; r++) {
        int gr = rowBase + ty * 8 + r;
        if (gr < NN) {
            float di = g_dinv[gr];
            if constexpr (BN == 128) {
                float2 f0 = unpack2(acc[r][0]), f1 = unpack2(acc[r][1]);
                __half2 h0 = __floats2half2_rn(f0.x * di, f0.y * di);
                __half2 h1 = __floats2half2_rn(f1.x * di, f1.y * di);
                uint2 u;
                u.x = *(unsigned*)&h0;
                u.y = *(unsigned*)&h1;
                ((uint2*)g_Hs1h)[gr * 32 + tx] = u;
            } else {
                float2 f0 = unpack2(acc[r][0]);
                __half2 h0 = __floats2half2_rn(f0.x * di, f0.y * di);
                g_Hs2h[gr * 32 + tx] = *(unsigned*)&h0;
            }
        }
    }
}

// ---------------- Aggregation (pull, CSR), one warp per node ----------------
// layer 1: gathers fp16 rows (256B/row), accumulates fp32, writes fp16 h.
__global__ void k_agg1(const float* __restrict__ b1) {
    int gw = (blockIdx.x * blockDim.x + threadIdx.x) >> 5;   // node id, exact
    int lane = threadIdx.x & 31;
    const uint2* __restrict__ H = (const uint2*)g_Hs1h;
    int beg = g_rowptr[gw], end = g_rowptr[gw + 1];
    uint2 sv = H[gw * 32 + lane];     // self term (pre-scaled by dinv[gw])
    float2 s0 = __half22float2(*(__half2*)&sv.x);
    float2 s1 = __half22float2(*(__half2*)&sv.y);
    float4 acc = make_float4(s0.x, s0.y, s1.x, s1.y);
    int j = beg;
    while (j < end) {
        int cnt = end - j; if (cnt > 32) cnt = 32;
        int idx = (lane < cnt) ? g_colidx[j + lane] : 0;
        int t = 0;
        for (; t + 4 <= cnt; t += 4) {
#pragma unroll
            for (int u = 0; u < 4; u++) {
                int s = __shfl_sync(0xffffffffu, idx, t + u);
                uint2 v = H[s * 32 + lane];
                float2 v0 = __half22float2(*(__half2*)&v.x);
                float2 v1 = __half22float2(*(__half2*)&v.y);
                acc.x += v0.x; acc.y += v0.y; acc.z += v1.x; acc.w += v1.y;
            }
        }
        for (; t < cnt; t++) {
            int s = __shfl_sync(0xffffffffu, idx, t);
            uint2 v = H[s * 32 + lane];
            float2 v0 = __half22float2(*(__half2*)&v.x);
            float2 v1 = __half22float2(*(__half2*)&v.y);
            acc.x += v0.x; acc.y += v0.y; acc.z += v1.x; acc.w += v1.y;
        }
        j += cnt;
    }
    float di = g_dinv[gw];
    float4 bb = ((const float4*)b1)[lane];
    float ox = fmaxf(fmaf(acc.x, di, bb.x), 0.f);
    float oy = fmaxf(fmaf(acc.y, di, bb.y), 0.f);
    float oz = fmaxf(fmaf(acc.z, di, bb.z), 0.f);
    float ow = fmaxf(fmaf(acc.w, di, bb.w), 0.f);
    __half2 h0 = __floats2half2_rn(ox, oy);
    __half2 h1 = __floats2half2_rn(oz, ow);
    uint2 u;
    u.x = *(unsigned*)&h0;
    u.y = *(unsigned*)&h1;
    ((uint2*)g_hh)[gw * 32 + lane] = u;
}

// layer 2: gathers fp16 rows (128B/row), accumulates fp32, writes fp32 out.
__global__ void k_agg2(const float* __restrict__ b2, float* __restrict__ outp) {
    int gw = (blockIdx.x * blockDim.x + threadIdx.x) >> 5;
    int lane = threadIdx.x & 31;
    const unsigned* __restrict__ H = g_Hs2h;
    int beg = g_rowptr[gw], end = g_rowptr[gw + 1];
    unsigned sv = H[gw * 32 + lane];
    float2 acc = __half22float2(*(__half2*)&sv);
    int j = beg;
    while (j < end) {
        int cnt = end - j; if (cnt > 32) cnt = 32;
        int idx = (lane < cnt) ? g_colidx[j + lane] : 0;
        int t = 0;
        for (; t + 4 <= cnt; t += 4) {
#pragma unroll
            for (int u = 0; u < 4; u++) {
                int s = __shfl_sync(0xffffffffu, idx, t + u);
                unsigned v = H[s * 32 + lane];
                float2 f = __half22float2(*(__half2*)&v);
                acc.x += f.x; acc.y += f.y;
            }
        }
        for (; t < cnt; t++) {
            int s = __shfl_sync(0xffffffffu, idx, t);
            unsigned v = H[s * 32 + lane];
            float2 f = __half22float2(*(__half2*)&v);
            acc.x += f.x; acc.y += f.y;
        }
        j += cnt;
    }
    float di = g_dinv[gw];
    float2 bb = ((const float2*)b2)[lane];
    ((float2*)outp)[gw * 32 + lane] =
        make_float2(fmaf(acc.x, di, bb.x), fmaf(acc.y, di, bb.y));
}

// ---------------- launch ----------------------------------------------------
extern "C" void kernel_launch(void* const* d_in, const int* in_sizes, int n_in,
                              void* d_out, int out_size) {
    // Identify inputs by element count (all six are distinct).
    const float* x  = 0;
    const float* W1 = 0;
    const float* b1 = 0;
    const float* W2 = 0;
    const float* b2 = 0;
    const void*  ei = 0;
    for (int i = 0; i < n_in; i++) {
        switch (in_sizes[i]) {
            case NN * 128:  x  = (const float*)d_in[i]; break;
            case 128 * 128: W1 = (const float*)d_in[i]; break;
            case 128:       b1 = (const float*)d_in[i]; break;
            case 128 * 64:  W2 = (const float*)d_in[i]; break;
            case 64:        b2 = (const float*)d_in[i]; break;
            case 2 * NE:    ei = (const void*)d_in[i];  break;
            default: break;
        }
    }

    const int EB4 = (NE / 4 + 255) / 256;     // 1563
    const int GB  = (NN + 63) / 64;           // 1563
    const int AB  = (NN / 8);                 // 12500 blocks * 8 warps

    // Serial pipeline (R4: overlapping memory-bound chains is net-negative).
    k_detect<<<1, 256>>>((const int*)ei);
    k_zero<<<(NN + 255) / 256, 256>>>();
    k_hist<<<EB4, 256>>>(ei);
    k_scan<<<NBLK, SCAN_B>>>();
    k_scatter<<<EB4, 256>>>(ei);

    k_gemm<128><<<GB, 256>>>(x, W1);
    k_agg1<<<AB, 256>>>(b1);
    k_gemm<64><<<GB, 256>>>(0, W2);
    k_agg2<<<AB, 256>>>(b2, (float*)d_out);
}

// round 11
// speedup vs baseline: 1.4350x; 1.4350x over previous
#include <cuda_runtime.h>
#include <cuda_fp16.h>

#define NN 100000
#define NE 1600000
#define SCAN_B 1024
#define NBLK ((NN + SCAN_B - 1) / SCAN_B)   // 98

// ---------------- scratch (static device globals; no runtime allocation) ----
__device__ unsigned g_Hs1h[NN * 64]; // (x@W1)*dinv, half2 pairs [N,128ch]
__device__ float    g_h [NN * 128];  // relu(layer1), fp32       [N,128]
__device__ unsigned g_Hs2h[NN * 32]; // (h@W2)*dinv, half2       [N,64ch]
__device__ int   g_count[NN];
__device__ float g_dinv[NN];
__device__ int   g_rowptr[NN + 1];
__device__ int   g_cursor[NN];
__device__ int   g_colidx[NE];
__device__ int   g_partial[128];
__device__ int   g_is64;            // 1 if edge_index is int64, 0 if int32

// ---------------- f32x2 helpers --------------------------------------------
__device__ __forceinline__ unsigned long long pack2(float a, float b) {
    unsigned long long r;
    asm("mov.b64 %0, {%1, %2};" : "=l"(r) : "f"(a), "f"(b));
    return r;
}
__device__ __forceinline__ void fma2(unsigned long long& d,
                                     unsigned long long a,
                                     unsigned long long b) {
    asm("fma.rn.f32x2 %0, %1, %2, %0;" : "+l"(d) : "l"(a), "l"(b));
}
__device__ __forceinline__ float2 unpack2(unsigned long long v) {
    float2 f;
    asm("mov.b64 {%0, %1}, %2;" : "=f"(f.x), "=f"(f.y) : "l"(v));
    return f;
}

// ---------------- CSR build -------------------------------------------------
// Zero counts; block 0 additionally sniffs the edge dtype:
// int64 ids < 2^31  =>  every odd int32 word is a zero high-word.
__global__ void k_zero(const int* __restrict__ ei32) {
    int i = blockIdx.x * blockDim.x + threadIdx.x;
    if (i < NN) g_count[i] = 0;
    if (blockIdx.x == 0) {
        __shared__ int s_or;
        if (threadIdx.x == 0) s_or = 0;
        __syncthreads();
        int v = ei32[2 * threadIdx.x + 1];
        if (v != 0) atomicOr(&s_or, 1);
        __syncthreads();
        if (threadIdx.x == 0) g_is64 = (s_or == 0) ? 1 : 0;
    }
}

// 4 edges per thread, vectorized index loads
__global__ void k_hist(const void* __restrict__ ei) {
    int q = blockIdx.x * blockDim.x + threadIdx.x;
    if (q >= NE / 4) return;
    int d0, d1, d2, d3;
    if (g_is64) {
        const long long* p = (const long long*)ei + NE + 4 * q;
        d0 = (int)p[0]; d1 = (int)p[1]; d2 = (int)p[2]; d3 = (int)p[3];
    } else {
        int4 v = ((const int4*)((const int*)ei + NE))[q];
        d0 = v.x; d1 = v.y; d2 = v.z; d3 = v.w;
    }
    if ((unsigned)d0 < (unsigned)NN) atomicAdd(&g_count[d0], 1);
    if ((unsigned)d1 < (unsigned)NN) atomicAdd(&g_count[d1], 1);
    if ((unsigned)d2 < (unsigned)NN) atomicAdd(&g_count[d2], 1);
    if ((unsigned)d3 < (unsigned)NN) atomicAdd(&g_count[d3], 1);
}

__global__ void k_scan1() {
    __shared__ int s[SCAN_B];
    int t = threadIdx.x;
    int i = blockIdx.x * SCAN_B + t;
    s[t] = (i < NN) ? g_count[i] : 0;
    __syncthreads();
    for (int off = SCAN_B / 2; off; off >>= 1) {
        if (t < off) s[t] += s[t + off];
        __syncthreads();
    }
    if (t == 0) g_partial[blockIdx.x] = s[0];
}

__global__ void k_scan2() {
    __shared__ int s[128];
    int t = threadIdx.x;
    s[t] = (t < NBLK) ? g_partial[t] : 0;
    __syncthreads();
    if (t == 0) {
        int run = 0;
        for (int b = 0; b < NBLK; b++) { int v = s[b]; s[b] = run; run += v; }
    }
    __syncthreads();
    if (t < NBLK) g_partial[t] = s[t];
}

__global__ void k_scan3() {
    __shared__ int s[SCAN_B];
    int t = threadIdx.x;
    int i = blockIdx.x * SCAN_B + t;
    int v = (i < NN) ? g_count[i] : 0;
    s[t] = v;
    __syncthreads();
    for (int off = 1; off < SCAN_B; off <<= 1) {
        int x = (t >= off) ? s[t - off] : 0;
        __syncthreads();
        s[t] += x;
        __syncthreads();
    }
    int excl = s[t] - v + g_partial[blockIdx.x];
    if (i < NN) {
        g_rowptr[i] = excl;
        g_cursor[i] = excl;
        g_dinv[i]   = rsqrtf((float)(v + 1));
    }
    if (i == NN - 1) g_rowptr[NN] = NE;
}

__global__ void k_scatter(const void* __restrict__ ei) {
    int q = blockIdx.x * blockDim.x + threadIdx.x;
    if (q >= NE / 4) return;
    int s0, s1, s2, s3, d0, d1, d2, d3;
    if (g_is64) {
        const long long* ps = (const long long*)ei + 4 * q;
        const long long* pd = (const long long*)ei + NE + 4 * q;
        s0 = (int)ps[0]; s1 = (int)ps[1]; s2 = (int)ps[2]; s3 = (int)ps[3];
        d0 = (int)pd[0]; d1 = (int)pd[1]; d2 = (int)pd[2]; d3 = (int)pd[3];
    } else {
        int4 vs = ((const int4*)ei)[q];
        int4 vd = ((const int4*)((const int*)ei + NE))[q];
        s0 = vs.x; s1 = vs.y; s2 = vs.z; s3 = vs.w;
        d0 = vd.x; d1 = vd.y; d2 = vd.z; d3 = vd.w;
    }
#define SCAT(ss, dd) \
    if ((unsigned)(dd) < (unsigned)NN && (unsigned)(ss) < (unsigned)NN) { \
        int pos = atomicAdd(&g_cursor[dd], 1); \
        if ((unsigned)pos < (unsigned)NE) g_colidx[pos] = (ss); }
    SCAT(s0, d0) SCAT(s1, d1) SCAT(s2, d2) SCAT(s3, d3)
#undef SCAT
}

// ---------------- GEMM:  Hs[m, BN] = (A[m, :128] @ W[:128, :BN]) * dinv[m] --
// 64 rows/block, 256 threads = (ty 0..7 -> 8 rows) x (tx 0..31 -> BN cols)
// A tile in 32KB smem (fp32); W streamed from global (<=64KB, L1-resident).
// BN==128: A = x (arg) -> writes g_Hs1h (fp16).  BN==64: A = g_h -> g_Hs2h (fp16).
template <int BN>
__global__ void k_gemm(const float* __restrict__ Ain,
                       const float* __restrict__ W) {
    __shared__ float As[64 * 128];   // 32 KB
    const int tid = threadIdx.x;
    const int tx = tid & 31, ty = tid >> 5;
    const int rowBase = blockIdx.x * 64;

    const float* Ap;
    if constexpr (BN == 128) Ap = Ain; else Ap = (const float*)g_h;

    {   // stage A tile (64x128), float4, guarded
        const float4* A4 = (const float4*)Ap;
        float4* As4 = (float4*)As;
#pragma unroll
        for (int i = 0; i < 8; i++) {
            int f = tid + i * 256;
            int r = f >> 5, c4 = f & 31;
            int gr = rowBase + r;
            As4[f] = (gr < NN) ? A4[gr * 32 + c4] : make_float4(0.f, 0.f, 0.f, 0.f);
        }
    }
    __syncthreads();

    constexpr int NP = BN / 64;
    unsigned long long acc[8][NP];
#pragma unroll
    for (int r = 0; r < 8; r++)
#pragma unroll
        for (int p = 0; p < NP; p++) acc[r][p] = 0ull;

    const float4* As4 = (const float4*)As;

#pragma unroll 4
    for (int k = 0; k < 128; k += 4) {
        unsigned long long breg[4][NP];
#pragma unroll
        for (int kk = 0; kk < 4; kk++) {
            if constexpr (NP == 2) {
                ulonglong2 bb = __ldg(&((const ulonglong2*)W)[(k + kk) * 32 + tx]);
                breg[kk][0] = bb.x; breg[kk][1] = bb.y;
            } else {
                breg[kk][0] = __ldg(&((const unsigned long long*)W)[(k + kk) * 32 + tx]);
            }
        }
#pragma unroll
        for (int r = 0; r < 8; r++) {
            float4 a4 = As4[(ty * 8 + r) * 32 + (k >> 2)];
            unsigned long long aa;
            aa = pack2(a4.x, a4.x);
#pragma unroll
            for (int p = 0; p < NP; p++) fma2(acc[r][p], aa, breg[0][p]);
            aa = pack2(a4.y, a4.y);
#pragma unroll
            for (int p = 0; p < NP; p++) fma2(acc[r][p], aa, breg[1][p]);
            aa = pack2(a4.z, a4.z);
#pragma unroll
            for (int p = 0; p < NP; p++) fma2(acc[r][p], aa, breg[2][p]);
            aa = pack2(a4.w, a4.w);
#pragma unroll
            for (int p = 0; p < NP; p++) fma2(acc[r][p], aa, breg[3][p]);
        }
    }

#pragma unroll
    for (int r = 0; r < 8; r++) {
        int gr = rowBase + ty * 8 + r;
        if (gr < NN) {
            float di = g_dinv[gr];
            if constexpr (BN == 128) {
                float2 f0 = unpack2(acc[r][0]), f1 = unpack2(acc[r][1]);
                __half2 h0 = __floats2half2_rn(f0.x * di, f0.y * di);
                __half2 h1 = __floats2half2_rn(f1.x * di, f1.y * di);
                uint2 u;
                u.x = *(unsigned*)&h0;
                u.y = *(unsigned*)&h1;
                ((uint2*)g_Hs1h)[gr * 32 + tx] = u;
            } else {
                float2 f0 = unpack2(acc[r][0]);
                __half2 h0 = __floats2half2_rn(f0.x * di, f0.y * di);
                g_Hs2h[gr * 32 + tx] = *(unsigned*)&h0;
            }
        }
    }
}

// ---------------- Aggregation (pull, CSR), one warp per node ----------------
// layer 1: gathers fp16 rows (256B/row), accumulates fp32, writes fp32 h.
__global__ void k_agg1(const float* __restrict__ b1) {
    int gw = (blockIdx.x * blockDim.x + threadIdx.x) >> 5;   // node id, exact
    int lane = threadIdx.x & 31;
    const uint2* __restrict__ H = (const uint2*)g_Hs1h;
    int beg = g_rowptr[gw], end = g_rowptr[gw + 1];
    uint2 sv = H[gw * 32 + lane];     // self term (pre-scaled by dinv[gw])
    float2 s0 = __half22float2(*(__half2*)&sv.x);
    float2 s1 = __half22float2(*(__half2*)&sv.y);
    float4 acc = make_float4(s0.x, s0.y, s1.x, s1.y);
    int j = beg;
    while (j < end) {
        int cnt = end - j; if (cnt > 32) cnt = 32;
        int idx = (lane < cnt) ? g_colidx[j + lane] : 0;
        int t = 0;
        for (; t + 4 <= cnt; t += 4) {
#pragma unroll
            for (int u = 0; u < 4; u++) {
                int s = __shfl_sync(0xffffffffu, idx, t + u);
                uint2 v = H[s * 32 + lane];
                float2 v0 = __half22float2(*(__half2*)&v.x);
                float2 v1 = __half22float2(*(__half2*)&v.y);
                acc.x += v0.x; acc.y += v0.y; acc.z += v1.x; acc.w += v1.y;
            }
        }
        for (; t < cnt; t++) {
            int s = __shfl_sync(0xffffffffu, idx, t);
            uint2 v = H[s * 32 + lane];
            float2 v0 = __half22float2(*(__half2*)&v.x);
            float2 v1 = __half22float2(*(__half2*)&v.y);
            acc.x += v0.x; acc.y += v0.y; acc.z += v1.x; acc.w += v1.y;
        }
        j += cnt;
    }
    float di = g_dinv[gw];
    float4 bb = ((const float4*)b1)[lane];
    float4 o;
    o.x = fmaxf(fmaf(acc.x, di, bb.x), 0.f);
    o.y = fmaxf(fmaf(acc.y, di, bb.y), 0.f);
    o.z = fmaxf(fmaf(acc.z, di, bb.z), 0.f);
    o.w = fmaxf(fmaf(acc.w, di, bb.w), 0.f);
    ((float4*)g_h)[gw * 32 + lane] = o;
}

// layer 2: gathers fp16 rows (128B/row), accumulates fp32, writes fp32 out.
__global__ void k_agg2(const float* __restrict__ b2, float* __restrict__ outp) {
    int gw = (blockIdx.x * blockDim.x + threadIdx.x) >> 5;
    int lane = threadIdx.x & 31;
    const unsigned* __restrict__ H = g_Hs2h;
    int beg = g_rowptr[gw], end = g_rowptr[gw + 1];
    unsigned sv = H[gw * 32 + lane];
    float2 acc = __half22float2(*(__half2*)&sv);
    int j = beg;
    while (j < end) {
        int cnt = end - j; if (cnt > 32) cnt = 32;
        int idx = (lane < cnt) ? g_colidx[j + lane] : 0;
        int t = 0;
        for (; t + 4 <= cnt; t += 4) {
#pragma unroll
            for (int u = 0; u < 4; u++) {
                int s = __shfl_sync(0xffffffffu, idx, t + u);
                unsigned v = H[s * 32 + lane];
                float2 f = __half22float2(*(__half2*)&v);
                acc.x += f.x; acc.y += f.y;
            }
        }
        for (; t < cnt; t++) {
            int s = __shfl_sync(0xffffffffu, idx, t);
            unsigned v = H[s * 32 + lane];
            float2 f = __half22float2(*(__half2*)&v);
            acc.x += f.x; acc.y += f.y;
        }
        j += cnt;
    }
    float di = g_dinv[gw];
    float2 bb = ((const float2*)b2)[lane];
    ((float2*)outp)[gw * 32 + lane] =
        make_float2(fmaf(acc.x, di, bb.x), fmaf(acc.y, di, bb.y));
}

// ---------------- launch ----------------------------------------------------
extern "C" void kernel_launch(void* const* d_in, const int* in_sizes, int n_in,
                              void* d_out, int out_size) {
    // Identify inputs by element count (all six are distinct).
    const float* x  = 0;
    const float* W1 = 0;
    const float* b1 = 0;
    const float* W2 = 0;
    const float* b2 = 0;
    const void*  ei = 0;
    for (int i = 0; i < n_in; i++) {
        switch (in_sizes[i]) {
            case NN * 128:  x  = (const float*)d_in[i]; break;
            case 128 * 128: W1 = (const float*)d_in[i]; break;
            case 128:       b1 = (const float*)d_in[i]; break;
            case 128 * 64:  W2 = (const float*)d_in[i]; break;
            case 64:        b2 = (const float*)d_in[i]; break;
            case 2 * NE:    ei = (const void*)d_in[i];  break;
            default: break;
        }
    }

    const int EB4 = (NE / 4 + 255) / 256;     // 1563
    const int GB  = (NN + 63) / 64;           // 1563
    const int AB  = (NN / 8);                 // 12500 blocks * 8 warps

    // Serial pipeline (R4: overlapping memory-bound chains is net-negative).
    k_zero<<<(NN + 255) / 256, 256>>>((const int*)ei);
    k_hist<<<EB4, 256>>>(ei);
    k_scan1<<<NBLK, SCAN_B>>>();
    k_scan2<<<1, 128>>>();
    k_scan3<<<NBLK, SCAN_B>>>();
    k_scatter<<<EB4, 256>>>(ei);

    k_gemm<128><<<GB, 256>>>(x, W1);
    k_agg1<<<AB, 256>>>(b1);
    k_gemm<64><<<GB, 256>>>(0, W2);
    k_agg2<<<AB, 256>>>(b2, (float*)d_out);
}

// round 12
// speedup vs baseline: 1.9991x; 1.3931x over previous
#include <cuda_runtime.h>
#include <cuda_fp16.h>

#define NN 100000
#define NE 1600000
#define SCAN_B 1024
#define NBLK ((NN + SCAN_B - 1) / SCAN_B)   // 98

// ---------------- scratch (static device globals; no runtime allocation) ----
__device__ unsigned g_Hs1h[NN * 64]; // (x@W1)*dinv, half2 pairs [N,128ch]
__device__ float    g_h [NN * 128];  // relu(layer1), fp32       [N,128]
__device__ unsigned g_Hs2h[NN * 32]; // (h@W2)*dinv, half2       [N,64ch]
__device__ __half   g_W1h[128 * 128];
__device__ __half   g_W2h[128 * 64];
__device__ int   g_count[NN];
__device__ float g_dinv[NN];
__device__ int   g_rowptr[NN + 1];
__device__ int   g_cursor[NN];
__device__ int   g_colidx[NE];
__device__ int   g_partial[128];
__device__ int   g_is64;            // 1 if edge_index is int64, 0 if int32

// ---------------- CSR build -------------------------------------------------
// Zero counts; block 0 additionally sniffs the edge dtype.
__global__ void k_zero(const int* __restrict__ ei32) {
    int i = blockIdx.x * blockDim.x + threadIdx.x;
    if (i < NN) g_count[i] = 0;
    if (blockIdx.x == 0) {
        __shared__ int s_or;
        if (threadIdx.x == 0) s_or = 0;
        __syncthreads();
        int v = ei32[2 * threadIdx.x + 1];
        if (v != 0) atomicOr(&s_or, 1);
        __syncthreads();
        if (threadIdx.x == 0) g_is64 = (s_or == 0) ? 1 : 0;
    }
}

__global__ void k_hist(const void* __restrict__ ei) {
    int q = blockIdx.x * blockDim.x + threadIdx.x;
    if (q >= NE / 4) return;
    int d0, d1, d2, d3;
    if (g_is64) {
        const long long* p = (const long long*)ei + NE + 4 * q;
        d0 = (int)p[0]; d1 = (int)p[1]; d2 = (int)p[2]; d3 = (int)p[3];
    } else {
        int4 v = ((const int4*)((const int*)ei + NE))[q];
        d0 = v.x; d1 = v.y; d2 = v.z; d3 = v.w;
    }
    if ((unsigned)d0 < (unsigned)NN) atomicAdd(&g_count[d0], 1);
    if ((unsigned)d1 < (unsigned)NN) atomicAdd(&g_count[d1], 1);
    if ((unsigned)d2 < (unsigned)NN) atomicAdd(&g_count[d2], 1);
    if ((unsigned)d3 < (unsigned)NN) atomicAdd(&g_count[d3], 1);
}

__global__ void k_scan1() {
    __shared__ int s[SCAN_B];
    int t = threadIdx.x;
    int i = blockIdx.x * SCAN_B + t;
    s[t] = (i < NN) ? g_count[i] : 0;
    __syncthreads();
    for (int off = SCAN_B / 2; off; off >>= 1) {
        if (t < off) s[t] += s[t + off];
        __syncthreads();
    }
    if (t == 0) g_partial[blockIdx.x] = s[0];
}

__global__ void k_scan2() {
    __shared__ int s[128];
    int t = threadIdx.x;
    s[t] = (t < NBLK) ? g_partial[t] : 0;
    __syncthreads();
    if (t == 0) {
        int run = 0;
        for (int b = 0; b < NBLK; b++) { int v = s[b]; s[b] = run; run += v; }
    }
    __syncthreads();
    if (t < NBLK) g_partial[t] = s[t];
}

__global__ void k_scan3() {
    __shared__ int s[SCAN_B];
    int t = threadIdx.x;
    int i = blockIdx.x * SCAN_B + t;
    int v = (i < NN) ? g_count[i] : 0;
    s[t] = v;
    __syncthreads();
    for (int off = 1; off < SCAN_B; off <<= 1) {
        int x = (t >= off) ? s[t - off] : 0;
        __syncthreads();
        s[t] += x;
        __syncthreads();
    }
    int excl = s[t] - v + g_partial[blockIdx.x];
    if (i < NN) {
        g_rowptr[i] = excl;
        g_cursor[i] = excl;
        g_dinv[i]   = rsqrtf((float)(v + 1));
    }
    if (i == NN - 1) g_rowptr[NN] = NE;
}

__global__ void k_scatter(const void* __restrict__ ei) {
    int q = blockIdx.x * blockDim.x + threadIdx.x;
    if (q >= NE / 4) return;
    int s0, s1, s2, s3, d0, d1, d2, d3;
    if (g_is64) {
        const long long* ps = (const long long*)ei + 4 * q;
        const long long* pd = (const long long*)ei + NE + 4 * q;
        s0 = (int)ps[0]; s1 = (int)ps[1]; s2 = (int)ps[2]; s3 = (int)ps[3];
        d0 = (int)pd[0]; d1 = (int)pd[1]; d2 = (int)pd[2]; d3 = (int)pd[3];
    } else {
        int4 vs = ((const int4*)ei)[q];
        int4 vd = ((const int4*)((const int*)ei + NE))[q];
        s0 = vs.x; s1 = vs.y; s2 = vs.z; s3 = vs.w;
        d0 = vd.x; d1 = vd.y; d2 = vd.z; d3 = vd.w;
    }
#define SCAT(ss, dd) \
    if ((unsigned)(dd) < (unsigned)NN && (unsigned)(ss) < (unsigned)NN) { \
        int pos = atomicAdd(&g_cursor[dd], 1); \
        if ((unsigned)pos < (unsigned)NE) g_colidx[pos] = (ss); }
    SCAT(s0, d0) SCAT(s1, d1) SCAT(s2, d2) SCAT(s3, d3)
#undef SCAT
}

// ---------------- W -> fp16 conversion ---------------------------------------
__global__ void k_wconv(const float* __restrict__ W1,
                        const float* __restrict__ W2) {
    int i = blockIdx.x * blockDim.x + threadIdx.x;
    if (i < 128 * 128) g_W1h[i] = __float2half_rn(W1[i]);
    else {
        int j = i - 128 * 128;
        if (j < 128 * 64) g_W2h[j] = __float2half_rn(W2[j]);
    }
}

// ---------------- Tensor-core GEMM -------------------------------------------
// Hs[m, BN] = (A[m, :128] @ W[:128, :BN]) * dinv[m], fp16 inputs, fp32 accum.
// Block = 32 rows, 256 threads (8 warps: 2 m-warps x 4 n-warps).
// A tile [32][128] fp16 + full W [128][BN] fp16 in smem, XOR-swizzled 16B
// chunks (chunk c of row r lives at c ^ (r&7)) for conflict-free ldmatrix.
// BN==128: A = x (fp32 arg), W = g_W1h -> writes g_Hs1h (half2).
// BN==64 : A = g_h (fp32),   W = g_W2h -> writes g_Hs2h (half2).
template <int BN>
__global__ void k_gemm_mma(const float* __restrict__ Ain) {
    __shared__ __align__(16) __half As[32 * 128];
    __shared__ __align__(16) __half Bs[128 * BN];
    const int tid = threadIdx.x;
    const int lane = tid & 31, wid = tid >> 5;
    const int warpM = wid & 1;          // 0..1  -> 16 rows each
    const int warpN = wid >> 1;         // 0..3  -> BN/4 cols each
    const int rowBase = blockIdx.x * 32;  // 3125 * 32 == 100000 exactly

    // ---- stage A (32 rows x 16 chunks of 16B), fp32 -> fp16, swizzled
    {
        const float4* A4 = (const float4*)((BN == 128) ? Ain : (const float*)g_h);
        uint4* As4 = (uint4*)As;
#pragma unroll
        for (int i = 0; i < 2; i++) {
            int f = tid + i * 256;          // 0..511
            int r = f >> 4, c = f & 15;
            int gr = rowBase + r;
            float4 lo = A4[gr * 32 + c * 2];
            float4 hi = A4[gr * 32 + c * 2 + 1];
            __half2 h0 = __floats2half2_rn(lo.x, lo.y);
            __half2 h1 = __floats2half2_rn(lo.z, lo.w);
            __half2 h2 = __floats2half2_rn(hi.x, hi.y);
            __half2 h3 = __floats2half2_rn(hi.z, hi.w);
            uint4 u;
            u.x = *(unsigned*)&h0; u.y = *(unsigned*)&h1;
            u.z = *(unsigned*)&h2; u.w = *(unsigned*)&h3;
            As4[r * 16 + (c ^ (r & 7))] = u;
        }
    }
    // ---- stage W (128 rows x CH chunks), already fp16, swizzled
    {
        constexpr int CH = BN / 8;          // 16 or 8 chunks per row
        const uint4* Wx = (const uint4*)((BN == 128) ? g_W1h : g_W2h);
        uint4* Bs4 = (uint4*)Bs;
#pragma unroll
        for (int i = 0; i < (128 * CH) / 256; i++) {
            int f = tid + i * 256;
            int k = f / CH, c = f % CH;
            Bs4[k * CH + (c ^ (k & 7))] = Wx[f];
        }
    }
    __syncthreads();

    constexpr int NT = BN / 32;             // n8-tiles per warp: 4 or 2
    float acc[NT][4];
#pragma unroll
    for (int n = 0; n < NT; n++)
#pragma unroll
        for (int q = 0; q < 4; q++) acc[n][q] = 0.f;

    unsigned aBase = (unsigned)__cvta_generic_to_shared(As);
    unsigned bBase = (unsigned)__cvta_generic_to_shared(Bs);
    const int r15 = lane & 15, seg = lane >> 4;
    const int arow = warpM * 16 + r15;

#pragma unroll
    for (int ks = 0; ks < 8; ks++) {
        // A fragment: m16 x k16 at (warpM*16, ks*16)
        unsigned a0, a1, a2, a3;
        {
            int cc = ks * 2 + seg;
            unsigned addr = aBase + arow * 256 + ((cc ^ (arow & 7)) << 4);
            asm volatile(
                "ldmatrix.sync.aligned.m8n8.x4.shared.b16 {%0,%1,%2,%3}, [%4];"
                : "=r"(a0), "=r"(a1), "=r"(a2), "=r"(a3) : "r"(addr));
        }
        int kk = ks * 16 + r15;             // B source row (k)
#pragma unroll
        for (int p = 0; p < NT / 2; p++) {
            int n0 = warpN * NT * 8 + p * 16;
            int cB = (n0 >> 3) + seg;
            unsigned addr = bBase + kk * (BN * 2) + ((cB ^ (kk & 7)) << 4);
            unsigned b0, b1, b2, b3;
            asm volatile(
                "ldmatrix.sync.aligned.m8n8.x4.trans.shared.b16 {%0,%1,%2,%3}, [%4];"
                : "=r"(b0), "=r"(b1), "=r"(b2), "=r"(b3) : "r"(addr));
            asm volatile(
                "mma.sync.aligned.m16n8k16.row.col.f32.f16.f16.f32 "
                "{%0,%1,%2,%3}, {%4,%5,%6,%7}, {%8,%9}, {%0,%1,%2,%3};"
                : "+f"(acc[2 * p][0]), "+f"(acc[2 * p][1]),
                  "+f"(acc[2 * p][2]), "+f"(acc[2 * p][3])
                : "r"(a0), "r"(a1), "r"(a2), "r"(a3), "r"(b0), "r"(b1));
            asm volatile(
                "mma.sync.aligned.m16n8k16.row.col.f32.f16.f16.f32 "
                "{%0,%1,%2,%3}, {%4,%5,%6,%7}, {%8,%9}, {%0,%1,%2,%3};"
                : "+f"(acc[2 * p + 1][0]), "+f"(acc[2 * p + 1][1]),
                  "+f"(acc[2 * p + 1][2]), "+f"(acc[2 * p + 1][3])
                : "r"(a0), "r"(a1), "r"(a2), "r"(a3), "r"(b2), "r"(b3));
        }
    }

    // ---- epilogue: * dinv, pack half2, store to gather buffer
    const int g = lane >> 2, tig = lane & 3;
    const int row1 = rowBase + warpM * 16 + g;
    const int row2 = row1 + 8;
    const float d1 = g_dinv[row1], d2 = g_dinv[row2];
    constexpr int ROWW = BN / 2;            // half2 words per row: 64 or 32
    unsigned* outp = (BN == 128) ? g_Hs1h : g_Hs2h;
#pragma unroll
    for (int nt = 0; nt < NT; nt++) {
        int col = warpN * NT * 8 + nt * 8 + tig * 2;
        int cp = col >> 1;
        __half2 u1 = __floats2half2_rn(acc[nt][0] * d1, acc[nt][1] * d1);
        __half2 u2 = __floats2half2_rn(acc[nt][2] * d2, acc[nt][3] * d2);
        outp[row1 * ROWW + cp] = *(unsigned*)&u1;
        outp[row2 * ROWW + cp] = *(unsigned*)&u2;
    }
}

// ---------------- Aggregation (pull, CSR), one warp per node ----------------
// layer 1: gathers fp16 rows (256B/row), accumulates fp32, writes fp32 h.
__global__ void k_agg1(const float* __restrict__ b1) {
    int gw = (blockIdx.x * blockDim.x + threadIdx.x) >> 5;   // node id, exact
    int lane = threadIdx.x & 31;
    const uint2* __restrict__ H = (const uint2*)g_Hs1h;
    int beg = g_rowptr[gw], end = g_rowptr[gw + 1];
    uint2 sv = H[gw * 32 + lane];     // self term (pre-scaled by dinv[gw])
    float2 s0 = __half22float2(*(__half2*)&sv.x);
    float2 s1 = __half22float2(*(__half2*)&sv.y);
    float4 acc = make_float4(s0.x, s0.y, s1.x, s1.y);
    int j = beg;
    while (j < end) {
        int cnt = end - j; if (cnt > 32) cnt = 32;
        int idx = (lane < cnt) ? g_colidx[j + lane] : 0;
        int t = 0;
        for (; t + 4 <= cnt; t += 4) {
#pragma unroll
            for (int u = 0; u < 4; u++) {
                int s = __shfl_sync(0xffffffffu, idx, t + u);
                uint2 v = H[s * 32 + lane];
                float2 v0 = __half22float2(*(__half2*)&v.x);
                float2 v1 = __half22float2(*(__half2*)&v.y);
                acc.x += v0.x; acc.y += v0.y; acc.z += v1.x; acc.w += v1.y;
            }
        }
        for (; t < cnt; t++) {
            int s = __shfl_sync(0xffffffffu, idx, t);
            uint2 v = H[s * 32 + lane];
            float2 v0 = __half22float2(*(__half2*)&v.x);
            float2 v1 = __half22float2(*(__half2*)&v.y);
            acc.x += v0.x; acc.y += v0.y; acc.z += v1.x; acc.w += v1.y;
        }
        j += cnt;
    }
    float di = g_dinv[gw];
    float4 bb = ((const float4*)b1)[lane];
    float4 o;
    o.x = fmaxf(fmaf(acc.x, di, bb.x), 0.f);
    o.y = fmaxf(fmaf(acc.y, di, bb.y), 0.f);
    o.z = fmaxf(fmaf(acc.z, di, bb.z), 0.f);
    o.w = fmaxf(fmaf(acc.w, di, bb.w), 0.f);
    ((float4*)g_h)[gw * 32 + lane] = o;
}

// layer 2: gathers fp16 rows (128B/row), accumulates fp32, writes fp32 out.
__global__ void k_agg2(const float* __restrict__ b2, float* __restrict__ outp) {
    int gw = (blockIdx.x * blockDim.x + threadIdx.x) >> 5;
    int lane = threadIdx.x & 31;
    const unsigned* __restrict__ H = g_Hs2h;
    int beg = g_rowptr[gw], end = g_rowptr[gw + 1];
    unsigned sv = H[gw * 32 + lane];
    float2 acc = __half22float2(*(__half2*)&sv);
    int j = beg;
    while (j < end) {
        int cnt = end - j; if (cnt > 32) cnt = 32;
        int idx = (lane < cnt) ? g_colidx[j + lane] : 0;
        int t = 0;
        for (; t + 4 <= cnt; t += 4) {
#pragma unroll
            for (int u = 0; u < 4; u++) {
                int s = __shfl_sync(0xffffffffu, idx, t + u);
                unsigned v = H[s * 32 + lane];
                float2 f = __half22float2(*(__half2*)&v);
                acc.x += f.x; acc.y += f.y;
            }
        }
        for (; t < cnt; t++) {
            int s = __shfl_sync(0xffffffffu, idx, t);
            unsigned v = H[s * 32 + lane];
            float2 f = __half22float2(*(__half2*)&v);
            acc.x += f.x; acc.y += f.y;
        }
        j += cnt;
    }
    float di = g_dinv[gw];
    float2 bb = ((const float2*)b2)[lane];
    ((float2*)outp)[gw * 32 + lane] =
        make_float2(fmaf(acc.x, di, bb.x), fmaf(acc.y, di, bb.y));
}

// ---------------- launch ----------------------------------------------------
extern "C" void kernel_launch(void* const* d_in, const int* in_sizes, int n_in,
                              void* d_out, int out_size) {
    // Identify inputs by element count (all six are distinct).
    const float* x  = 0;
    const float* W1 = 0;
    const float* b1 = 0;
    const float* W2 = 0;
    const float* b2 = 0;
    const void*  ei = 0;
    for (int i = 0; i < n_in; i++) {
        switch (in_sizes[i]) {
            case NN * 128:  x  = (const float*)d_in[i]; break;
            case 128 * 128: W1 = (const float*)d_in[i]; break;
            case 128:       b1 = (const float*)d_in[i]; break;
            case 128 * 64:  W2 = (const float*)d_in[i]; break;
            case 64:        b2 = (const float*)d_in[i]; break;
            case 2 * NE:    ei = (const void*)d_in[i];  break;
            default: break;
        }
    }

    const int EB4 = (NE / 4 + 255) / 256;     // 1563
    const int GB  = NN / 32;                  // 3125 (exact)
    const int AB  = (NN / 8);                 // 12500 blocks * 8 warps

    // Serial pipeline (R4: overlapping memory-bound chains is net-negative).
    k_wconv<<<96, 256>>>(W1, W2);
    k_zero<<<(NN + 255) / 256, 256>>>((const int*)ei);
    k_hist<<<EB4, 256>>>(ei);
    k_scan1<<<NBLK, SCAN_B>>>();
    k_scan2<<<1, 128>>>();
    k_scan3<<<NBLK, SCAN_B>>>();
    k_scatter<<<EB4, 256>>>(ei);

    k_gemm_mma<128><<<GB, 256>>>(x);
    k_agg1<<<AB, 256>>>(b1);
    k_gemm_mma<64><<<GB, 256>>>(0);
    k_agg2<<<AB, 256>>>(b2, (float*)d_out);
}

// round 14
// speedup vs baseline: 2.0791x; 1.0400x over previous
#include <cuda_runtime.h>
#include <cuda_fp16.h>

#define NN 100000
#define NE 1600000
#define SCAN_B 1024
#define NBLK ((NN + SCAN_B - 1) / SCAN_B)   // 98

// ---------------- scratch (static device globals; no runtime allocation) ----
__device__ unsigned g_Hs1h[NN * 64]; // (x@W1)*dinv, half2 pairs [N,128ch]
__device__ unsigned g_hh  [NN * 64]; // relu(layer1), half2 pairs [N,128ch]
__device__ unsigned g_Hs2h[NN * 32]; // (h@W2)*dinv, half2       [N,64ch]
__device__ __half   g_W1h[128 * 128];
__device__ __half   g_W2h[128 * 64];
__device__ int   g_count[NN];
__device__ float g_dinv[NN];
__device__ int   g_rowptr[NN + 1];
__device__ int   g_cursor[NN];
__device__ int   g_colidx[NE];
__device__ int   g_partial[128];
__device__ int   g_is64;            // 1 if edge_index is int64, 0 if int32

// ---------------- CSR build -------------------------------------------------
// Zero counts + convert W1/W2 to fp16; block 0 additionally sniffs edge dtype.
__global__ void k_zero(const int* __restrict__ ei32,
                       const float* __restrict__ W1,
                       const float* __restrict__ W2) {
    int i = blockIdx.x * blockDim.x + threadIdx.x;
    if (i < NN) g_count[i] = 0;
    if (i < 128 * 128) g_W1h[i] = __float2half_rn(W1[i]);
    if (i < 128 * 64)  g_W2h[i] = __float2half_rn(W2[i]);
    if (blockIdx.x == 0) {
        __shared__ int s_or;
        if (threadIdx.x == 0) s_or = 0;
        __syncthreads();
        int v = ei32[2 * threadIdx.x + 1];
        if (v != 0) atomicOr(&s_or, 1);
        __syncthreads();
        if (threadIdx.x == 0) g_is64 = (s_or == 0) ? 1 : 0;
    }
}

__global__ void k_hist(const void* __restrict__ ei) {
    int q = blockIdx.x * blockDim.x + threadIdx.x;
    if (q >= NE / 4) return;
    int d0, d1, d2, d3;
    if (g_is64) {
        const long long* p = (const long long*)ei + NE + 4 * q;
        d0 = (int)p[0]; d1 = (int)p[1]; d2 = (int)p[2]; d3 = (int)p[3];
    } else {
        int4 v = ((const int4*)((const int*)ei + NE))[q];
        d0 = v.x; d1 = v.y; d2 = v.z; d3 = v.w;
    }
    if ((unsigned)d0 < (unsigned)NN) atomicAdd(&g_count[d0], 1);
    if ((unsigned)d1 < (unsigned)NN) atomicAdd(&g_count[d1], 1);
    if ((unsigned)d2 < (unsigned)NN) atomicAdd(&g_count[d2], 1);
    if ((unsigned)d3 < (unsigned)NN) atomicAdd(&g_count[d3], 1);
}

__global__ void k_scan1() {
    __shared__ int s[SCAN_B];
    int t = threadIdx.x;
    int i = blockIdx.x * SCAN_B + t;
    s[t] = (i < NN) ? g_count[i] : 0;
    __syncthreads();
    for (int off = SCAN_B / 2; off; off >>= 1) {
        if (t < off) s[t] += s[t + off];
        __syncthreads();
    }
    if (t == 0) g_partial[blockIdx.x] = s[0];
}

__global__ void k_scan2() {
    __shared__ int s[128];
    int t = threadIdx.x;
    s[t] = (t < NBLK) ? g_partial[t] : 0;
    __syncthreads();
    if (t == 0) {
        int run = 0;
        for (int b = 0; b < NBLK; b++) { int v = s[b]; s[b] = run; run += v; }
    }
    __syncthreads();
    if (t < NBLK) g_partial[t] = s[t];
}

__global__ void k_scan3() {
    __shared__ int s[SCAN_B];
    int t = threadIdx.x;
    int i = blockIdx.x * SCAN_B + t;
    int v = (i < NN) ? g_count[i] : 0;
    s[t] = v;
    __syncthreads();
    for (int off = 1; off < SCAN_B; off <<= 1) {
        int x = (t >= off) ? s[t - off] : 0;
        __syncthreads();
        s[t] += x;
        __syncthreads();
    }
    int excl = s[t] - v + g_partial[blockIdx.x];
    if (i < NN) {
        g_rowptr[i] = excl;
        g_cursor[i] = excl;
        g_dinv[i]   = rsqrtf((float)(v + 1));
    }
    if (i == NN - 1) g_rowptr[NN] = NE;
}

__global__ void k_scatter(const void* __restrict__ ei) {
    int q = blockIdx.x * blockDim.x + threadIdx.x;
    if (q >= NE / 4) return;
    int s0, s1, s2, s3, d0, d1, d2, d3;
    if (g_is64) {
        const long long* ps = (const long long*)ei + 4 * q;
        const long long* pd = (const long long*)ei + NE + 4 * q;
        s0 = (int)ps[0]; s1 = (int)ps[1]; s2 = (int)ps[2]; s3 = (int)ps[3];
        d0 = (int)pd[0]; d1 = (int)pd[1]; d2 = (int)pd[2]; d3 = (int)pd[3];
    } else {
        int4 vs = ((const int4*)ei)[q];
        int4 vd = ((const int4*)((const int*)ei + NE))[q];
        s0 = vs.x; s1 = vs.y; s2 = vs.z; s3 = vs.w;
        d0 = vd.x; d1 = vd.y; d2 = vd.z; d3 = vd.w;
    }
#define SCAT(ss, dd) \
    if ((unsigned)(dd) < (unsigned)NN && (unsigned)(ss) < (unsigned)NN) { \
        int pos = atomicAdd(&g_cursor[dd], 1); \
        if ((unsigned)pos < (unsigned)NE) g_colidx[pos] = (ss); }
    SCAT(s0, d0) SCAT(s1, d1) SCAT(s2, d2) SCAT(s3, d3)
#undef SCAT
}

// ---------------- Tensor-core GEMM -------------------------------------------
// Hs[m, BN] = (A[m, :128] @ W[:128, :BN]) * dinv[m], fp16 inputs, fp32 accum.
// Block = 32 rows, 256 threads (8 warps: 2 m-warps x 4 n-warps).
// A tile [32][128] fp16 + full W [128][BN] fp16 in smem, XOR-swizzled 16B
// chunks (chunk c of row r lives at c ^ (r&7)) for conflict-free ldmatrix.
// BN==128: A = x (fp32 arg), W = g_W1h -> writes g_Hs1h (half2).
// BN==64 : A = g_hh (fp16),  W = g_W2h -> writes g_Hs2h (half2).
template <int BN>
__global__ void k_gemm_mma(const float* __restrict__ Ain) {
    __shared__ __align__(16) __half As[32 * 128];
    __shared__ __align__(16) __half Bs[128 * BN];
    const int tid = threadIdx.x;
    const int lane = tid & 31, wid = tid >> 5;
    const int warpM = wid & 1;          // 0..1  -> 16 rows each
    const int warpN = wid >> 1;         // 0..3  -> BN/4 cols each
    const int rowBase = blockIdx.x * 32;  // 3125 * 32 == 100000 exactly

    // ---- stage A (32 rows x 16 chunks of 16B), swizzled
    if constexpr (BN == 128) {          // from fp32 x, convert to fp16
        const float4* A4 = (const float4*)Ain;
        uint4* As4 = (uint4*)As;
#pragma unroll
        for (int i = 0; i < 2; i++) {
            int f = tid + i * 256;          // 0..511
            int r = f >> 4, c = f & 15;
            int gr = rowBase + r;
            float4 lo = A4[gr * 32 + c * 2];
            float4 hi = A4[gr * 32 + c * 2 + 1];
            __half2 h0 = __floats2half2_rn(lo.x, lo.y);
            __half2 h1 = __floats2half2_rn(lo.z, lo.w);
            __half2 h2 = __floats2half2_rn(hi.x, hi.y);
            __half2 h3 = __floats2half2_rn(hi.z, hi.w);
            uint4 u;
            u.x = *(unsigned*)&h0; u.y = *(unsigned*)&h1;
            u.z = *(unsigned*)&h2; u.w = *(unsigned*)&h3;
            As4[r * 16 + (c ^ (r & 7))] = u;
        }
    } else {                            // from fp16 g_hh, pure copy
        const uint4* A4 = (const uint4*)g_hh;   // 16 uint4 per 128-ch row
        uint4* As4 = (uint4*)As;
#pragma unroll
        for (int i = 0; i < 2; i++) {
            int f = tid + i * 256;          // 0..511
            int r = f >> 4, c = f & 15;
            As4[r * 16 + (c ^ (r & 7))] = A4[(rowBase + r) * 16 + c];
        }
    }
    // ---- stage W (128 rows x CH chunks), already fp16, swizzled
    {
        constexpr int CH = BN / 8;          // 16 or 8 chunks per row
        const uint4* Wx = (const uint4*)((BN == 128) ? g_W1h : g_W2h);
        uint4* Bs4 = (uint4*)Bs;
#pragma unroll
        for (int i = 0; i < (128 * CH) / 256; i++) {
            int f = tid + i * 256;
            int k = f / CH, c = f % CH;
            Bs4[k * CH + (c ^ (k & 7))] = Wx[f];
        }
    }
    __syncthreads();

    constexpr int NT = BN / 32;             // n8-tiles per warp: 4 or 2
    float acc[NT][4];
#pragma unroll
    for (int n = 0; n < NT; n++)
#pragma unroll
        for (int q = 0; q < 4; q++) acc[n][q] = 0.f;

    unsigned aBase = (unsigned)__cvta_generic_to_shared(As);
    unsigned bBase = (unsigned)__cvta_generic_to_shared(Bs);
    const int r15 = lane & 15, seg = lane >> 4;
    const int arow = warpM * 16 + r15;

#pragma unroll
    for (int ks = 0; ks < 8; ks++) {
        // A fragment: m16 x k16 at (warpM*16, ks*16)
        unsigned a0, a1, a2, a3;
        {
            int cc = ks * 2 + seg;
            unsigned addr = aBase + arow * 256 + ((cc ^ (arow & 7)) << 4);
            asm volatile(
                "ldmatrix.sync.aligned.m8n8.x4.shared.b16 {%0,%1,%2,%3}, [%4];"
                : "=r"(a0), "=r"(a1), "=r"(a2), "=r"(a3) : "r"(addr));
        }
        int kk = ks * 16 + r15;             // B source row (k)
#pragma unroll
        for (int p = 0; p < NT / 2; p++) {
            int n0 = warpN * NT * 8 + p * 16;
            int cB = (n0 >> 3) + seg;
            unsigned addr = bBase + kk * (BN * 2) + ((cB ^ (kk & 7)) << 4);
            unsigned b0, b1, b2, b3;
            asm volatile(
                "ldmatrix.sync.aligned.m8n8.x4.trans.shared.b16 {%0,%1,%2,%3}, [%4];"
                : "=r"(b0), "=r"(b1), "=r"(b2), "=r"(b3) : "r"(addr));
            asm volatile(
                "mma.sync.aligned.m16n8k16.row.col.f32.f16.f16.f32 "
                "{%0,%1,%2,%3}, {%4,%5,%6,%7}, {%8,%9}, {%0,%1,%2,%3};"
                : "+f"(acc[2 * p][0]), "+f"(acc[2 * p][1]),
                  "+f"(acc[2 * p][2]), "+f"(acc[2 * p][3])
                : "r"(a0), "r"(a1), "r"(a2), "r"(a3), "r"(b0), "r"(b1));
            asm volatile(
                "mma.sync.aligned.m16n8k16.row.col.f32.f16.f16.f32 "
                "{%0,%1,%2,%3}, {%4,%5,%6,%7}, {%8,%9}, {%0,%1,%2,%3};"
                : "+f"(acc[2 * p + 1][0]), "+f"(acc[2 * p + 1][1]),
                  "+f"(acc[2 * p + 1][2]), "+f"(acc[2 * p + 1][3])
                : "r"(a0), "r"(a1), "r"(a2), "r"(a3), "r"(b2), "r"(b3));
        }
    }

    // ---- epilogue: * dinv, pack half2, store to gather buffer
    const int g = lane >> 2, tig = lane & 3;
    const int row1 = rowBase + warpM * 16 + g;
    const int row2 = row1 + 8;
    const float d1 = g_dinv[row1], d2 = g_dinv[row2];
    constexpr int ROWW = BN / 2;            // half2 words per row: 64 or 32
    unsigned* outp = (BN == 128) ? g_Hs1h : g_Hs2h;
#pragma unroll
    for (int nt = 0; nt < NT; nt++) {
        int col = warpN * NT * 8 + nt * 8 + tig * 2;
        int cp = col >> 1;
        __half2 u1 = __floats2half2_rn(acc[nt][0] * d1, acc[nt][1] * d1);
        __half2 u2 = __floats2half2_rn(acc[nt][2] * d2, acc[nt][3] * d2);
        outp[row1 * ROWW + cp] = *(unsigned*)&u1;
        outp[row2 * ROWW + cp] = *(unsigned*)&u2;
    }
}

// ---------------- Aggregation (pull, CSR), one warp per node ----------------
// layer 1: gathers fp16 rows (256B/row), accumulates fp32, writes fp16 h.
__global__ void k_agg1(const float* __restrict__ b1) {
    int gw = (blockIdx.x * blockDim.x + threadIdx.x) >> 5;   // node id, exact
    int lane = threadIdx.x & 31;
    const uint2* __restrict__ H = (const uint2*)g_Hs1h;
    int beg = g_rowptr[gw], end = g_rowptr[gw + 1];
    uint2 sv = H[gw * 32 + lane];     // self term (pre-scaled by dinv[gw])
    float2 s0 = __half22float2(*(__half2*)&sv.x);
    float2 s1 = __half22float2(*(__half2*)&sv.y);
    float4 acc = make_float4(s0.x, s0.y, s1.x, s1.y);
    int j = beg;
    while (j < end) {
        int cnt = end - j; if (cnt > 32) cnt = 32;
        int idx = (lane < cnt) ? g_colidx[j + lane] : 0;
        int t = 0;
        for (; t + 4 <= cnt; t += 4) {
#pragma unroll
            for (int u = 0; u < 4; u++) {
                int s = __shfl_sync(0xffffffffu, idx, t + u);
                uint2 v = H[s * 32 + lane];
                float2 v0 = __half22float2(*(__half2*)&v.x);
                float2 v1 = __half22float2(*(__half2*)&v.y);
                acc.x += v0.x; acc.y += v0.y; acc.z += v1.x; acc.w += v1.y;
            }
        }
        for (; t < cnt; t++) {
            int s = __shfl_sync(0xffffffffu, idx, t);
            uint2 v = H[s * 32 + lane];
            float2 v0 = __half22float2(*(__half2*)&v.x);
            float2 v1 = __half22float2(*(__half2*)&v.y);
            acc.x += v0.x; acc.y += v0.y; acc.z += v1.x; acc.w += v1.y;
        }
        j += cnt;
    }
    float di = g_dinv[gw];
    float4 bb = ((const float4*)b1)[lane];
    float ox = fmaxf(fmaf(acc.x, di, bb.x), 0.f);
    float oy = fmaxf(fmaf(acc.y, di, bb.y), 0.f);
    float oz = fmaxf(fmaf(acc.z, di, bb.z), 0.f);
    float ow = fmaxf(fmaf(acc.w, di, bb.w), 0.f);
    __half2 h0 = __floats2half2_rn(ox, oy);
    __half2 h1 = __floats2half2_rn(oz, ow);
    uint2 u;
    u.x = *(unsigned*)&h0;
    u.y = *(unsigned*)&h1;
    ((uint2*)g_hh)[gw * 32 + lane] = u;
}

// layer 2: gathers fp16 rows (128B/row), accumulates fp32, writes fp32 out.
__global__ void k_agg2(const float* __restrict__ b2, float* __restrict__ outp) {
    int gw = (blockIdx.x * blockDim.x + threadIdx.x) >> 5;
    int lane = threadIdx.x & 31;
    const unsigned* __restrict__ H = g_Hs2h;
    int beg = g_rowptr[gw], end = g_rowptr[gw + 1];
    unsigned sv = H[gw * 32 + lane];
    float2 acc = __half22float2(*(__half2*)&sv);
    int j = beg;
    while (j < end) {
        int cnt = end - j; if (cnt > 32) cnt = 32;
        int idx = (lane < cnt) ? g_colidx[j + lane] : 0;
        int t = 0;
        for (; t + 4 <= cnt; t += 4) {
#pragma unroll
            for (int u = 0; u < 4; u++) {
                int s = __shfl_sync(0xffffffffu, idx, t + u);
                unsigned v = H[s * 32 + lane];
                float2 f = __half22float2(*(__half2*)&v);
                acc.x += f.x; acc.y += f.y;
            }
        }
        for (; t < cnt; t++) {
            int s = __shfl_sync(0xffffffffu, idx, t);
            unsigned v = H[s * 32 + lane];
            float2 f = __half22float2(*(__half2*)&v);
            acc.x += f.x; acc.y += f.y;
        }
        j += cnt;
    }
    float di = g_dinv[gw];
    float2 bb = ((const float2*)b2)[lane];
    ((float2*)outp)[gw * 32 + lane] =
        make_float2(fmaf(acc.x, di, bb.x), fmaf(acc.y, di, bb.y));
}

// ---------------- launch ----------------------------------------------------
extern "C" void kernel_launch(void* const* d_in, const int* in_sizes, int n_in,
                              void* d_out, int out_size) {
    // Identify inputs by element count (all six are distinct).
    const float* x  = 0;
    const float* W1 = 0;
    const float* b1 = 0;
    const float* W2 = 0;
    const float* b2 = 0;
    const void*  ei = 0;
    for (int i = 0; i < n_in; i++) {
        switch (in_sizes[i]) {
            case NN * 128:  x  = (const float*)d_in[i]; break;
            case 128 * 128: W1 = (const float*)d_in[i]; break;
            case 128:       b1 = (const float*)d_in[i]; break;
            case 128 * 64:  W2 = (const float*)d_in[i]; break;
            case 64:        b2 = (const float*)d_in[i]; break;
            case 2 * NE:    ei = (const void*)d_in[i];  break;
            default: break;
        }
    }

    const int EB4 = (NE / 4 + 255) / 256;     // 1563
    const int GB  = NN / 32;                  // 3125 (exact)
    const int AB  = (NN / 8);                 // 12500 blocks * 8 warps

    // Serial pipeline (R4: overlapping memory-bound chains is net-negative).
    k_zero<<<(NN + 255) / 256, 256>>>((const int*)ei, W1, W2);
    k_hist<<<EB4, 256>>>(ei);
    k_scan1<<<NBLK, SCAN_B>>>();
    k_scan2<<<1, 128>>>();
    k_scan3<<<NBLK, SCAN_B>>>();
    k_scatter<<<EB4, 256>>>(ei);

    k_gemm_mma<128><<<GB, 256>>>(x);
    k_agg1<<<AB, 256>>>(b1);
    k_gemm_mma<64><<<GB, 256>>>(0);
    k_agg2<<<AB, 256>>>(b2, (float*)d_out);
}